// round 15
// baseline (speedup 1.0000x reference)
#include <cuda_runtime.h>
#include <cstdint>

#define FULL_MASK 0xffffffffu
typedef unsigned long long u64;

// ---------- packed f32x2 helpers (sm_100+ SIMD fp32, PTX-only) ----------
__device__ __forceinline__ u64 pk(float lo, float hi) {
    u64 r; asm("mov.b64 %0,{%1,%2};" : "=l"(r) : "f"(lo), "f"(hi)); return r;
}
__device__ __forceinline__ void unpk(u64 v, float& lo, float& hi) {
    asm("mov.b64 {%0,%1},%2;" : "=f"(lo), "=f"(hi) : "l"(v));
}
__device__ __forceinline__ u64 add2(u64 a, u64 b) {
    u64 d; asm("add.rn.f32x2 %0,%1,%2;" : "=l"(d) : "l"(a), "l"(b)); return d;
}
__device__ __forceinline__ u64 mul2(u64 a, u64 b) {
    u64 d; asm("mul.rn.f32x2 %0,%1,%2;" : "=l"(d) : "l"(a), "l"(b)); return d;
}
__device__ __forceinline__ u64 fma2(u64 a, u64 b, u64 c) {
    u64 d; asm("fma.rn.f32x2 %0,%1,%2,%3;" : "=l"(d) : "l"(a), "l"(b), "l"(c)); return d;
}
__device__ __forceinline__ u64 abs2(u64 a) {   // clear both sign bits
    u64 d; asm("and.b64 %0,%1,0x7FFFFFFF7FFFFFFF;" : "=l"(d) : "l"(a)); return d;
}

// Problem geometry: (16, 1, 1024, 1024) fp32 pred/target, scalar fp32 out.
constexpr int W = 1024;
constexpr int H = 1024;
constexpr int PLANES = 16;

constexpr int OUTC   = 62;                 // valid outputs per 64-col warp strip
constexpr int STRIPS = 17;                 // 62*17 = 1054 >= 1024
constexpr int RY     = 64;                 // rows per warp band (single wave, less halo)
constexpr int BANDS  = H / RY;             // 16
constexpr int TOTAL_WARPS = STRIPS * BANDS * PLANES;  // 4352
constexpr int WPB    = 8;                  // 256 threads per block
constexpr int NBLOCKS = TOTAL_WARPS / WPB; // 544  (<= 148 SM * 4 CTA = 592: ONE wave)

// 81-scaled SSIM constants (window SUMS instead of means; 81^2 cancels)
constexpr float C1S = 81.0f * 0.0001f;
constexpr float C2S = 81.0f * 0.0009f;

__device__ float2   g_partials[NBLOCKS];
__device__ unsigned g_count = 0;

struct Hrow { u64 p, t, qq, pt; };   // horizontal 3-sums of one input row

__global__ void __launch_bounds__(WPB * 32, 4)   // <=64 regs
loss_main(const float* __restrict__ pred, const float* __restrict__ targ,
          float* __restrict__ out)
{
    const int warp  = blockIdx.x * WPB + (threadIdx.x >> 5);
    const int lane  = threadIdx.x & 31;
    const int strip = warp % STRIPS;
    const int band  = (warp / STRIPS) % BANDS;
    const int plane = warp / (STRIPS * BANDS);

    const int x0  = strip * OUTC + 2 * lane;       // even -> 8B aligned
    const bool xin = (x0 < W);

    const int y0 = band * RY;

    const float* __restrict__ pb0 =
        pred + (size_t)plane * (size_t)(W * H) + (size_t)y0 * W + x0;
    const float* __restrict__ tb0 =
        targ + (size_t)plane * (size_t)(W * H) + (size_t)y0 * W + x0;

    // hoisted packed constants (warp-uniform)
    const u64 C1S2  = pk(C1S, C1S);
    const u64 C2S2  = pk(C2S, C2S);
    const u64 E182  = pk(18.0f, 18.0f);
    const u64 NINE2 = pk(9.0f, 9.0f);
    const u64 NEG12 = pk(-1.0f, -1.0f);

    const bool valid0 = ((lane > 0) || (strip == 0)) && (x0 < W);
    const bool valid1 = (lane < 31) && (x0 + 1 < W);
    const u64 MASK2 = pk(valid0 ? 1.0f : 0.0f, valid1 ? 1.0f : 0.0f);

    u64 ssim_acc = 0ull;
    u64 l1_acc   = 0ull;

    // k is row offset relative to y0 (may be -1 .. RY)
    auto load_row = [&](int k, u64& p, u64& t) {
        p = 0ull; t = 0ull;
        if (xin && (unsigned)(y0 + k) < (unsigned)H) {
            p = *(const u64*)(pb0 + (ptrdiff_t)k * W);
            t = *(const u64*)(tb0 + (ptrdiff_t)k * W);
        }
    };

    // horizontal 3-sums + masked L1 for this row
    auto horiz = [&](u64 p64, u64 t64, u64 l1m) -> Hrow {
        float px, py, tx, ty;
        unpk(p64, px, py);
        unpk(t64, tx, ty);
        float pL = __shfl_up_sync(FULL_MASK, py, 1);
        float tL = __shfl_up_sync(FULL_MASK, ty, 1);
        float pR = __shfl_down_sync(FULL_MASK, px, 1);
        float tR = __shfl_down_sync(FULL_MASK, tx, 1);
        if (lane == 0) { pL = 0.0f; tL = 0.0f; }   // image-left zero pad

        const float cp  = px + py;
        const float ct  = tx + ty;
        const float cqq = fmaf(px, px, py * py) + fmaf(tx, tx, ty * ty);
        const float cpt = fmaf(px, tx, py * ty);

        const u64 pLR = pk(pL, pR);
        const u64 tLR = pk(tL, tR);
        Hrow h;
        h.p  = add2(pLR, pk(cp, cp));
        h.t  = add2(tLR, pk(ct, ct));
        h.qq = fma2(pLR, pLR, fma2(tLR, tLR, pk(cqq, cqq)));
        h.pt = fma2(pLR, tLR, pk(cpt, cpt));

        const u64 df = abs2(fma2(t64, NEG12, p64));
        l1_acc = fma2(df, l1m, l1_acc);
        return h;
    };

    // SSIM poly on a 3-row window; accumulate masked (0.5 - 0.5*ratio)
    auto poly_acc = [&](const Hrow& a, const Hrow& b, const Hrow& c) {
        const u64 SP  = add2(add2(a.p,  b.p),  c.p);
        const u64 ST  = add2(add2(a.t,  b.t),  c.t);
        const u64 Sqq = add2(add2(a.qq, b.qq), c.qq);
        const u64 SPT = add2(add2(a.pt, b.pt), c.pt);

        const u64 A   = mul2(SP, ST);
        const u64 A2  = add2(A, A);                 // 2*A
        const u64 B   = mul2(SP, SP);
        const u64 Cq  = mul2(ST, ST);
        const u64 n1  = add2(A2, C1S2);
        const u64 n2  = fma2(E182, SPT, fma2(A2, NEG12, C2S2));
        const u64 BC  = add2(B, Cq);
        const u64 d1  = add2(BC, C1S2);
        const u64 d2  = fma2(BC, NEG12, fma2(NINE2, Sqq, C2S2));
        const u64 num = mul2(n1, n2);
        const u64 den = mul2(d1, d2);    // >= C1S*C2S > 0

        float nx, ny, dx, dy;
        unpk(num, nx, ny);
        unpk(den, dx, dy);
        const float r0 = __fdividef(nx, dx);
        const float r1 = __fdividef(ny, dy);
        // ratio in [-1,1] exactly (AM-GM / Cauchy-Schwarz, C1,C2>0):
        // val = 0.5 - 0.5*ratio is already in [0,1]; reference clamp is a no-op.
        float v0 = fmaf(r0, -0.5f, 0.5f);
        float v1 = fmaf(r1, -0.5f, 0.5f);
        ssim_acc = fma2(pk(v0, v1), MASK2, ssim_acc);
    };

    // ---- prologue: h(-1), h(0) computed; raws of rows 1,2 in flight ----
    Hrow hA, hB;
    {
        u64 pA, tA;
        load_row(-1, pA, tA);
        hA = horiz(pA, tA, 0ull);      // top halo: no L1
        load_row(0, pA, tA);
        hB = horiz(pA, tA, MASK2);     // row y0
    }
    u64 rCp, rCt, rDp, rDt;
    load_row(1, rCp, rCt);
    load_row(2, rDp, rDt);

    // ---- main loop: 31 iters, 2 output rows each (rows 0..61) ----
    #pragma unroll 5
    for (int i = 0; i < (RY - 2) / 2; ++i) {
        const int k = 2 * i;

        // issue loads for rows k+3, k+4 (consumed next iteration)
        u64 rEp, rEt, rFp, rFt;
        load_row(k + 3, rEp, rEt);
        load_row(k + 4, rFp, rFt);

        // horiz for rows k+1, k+2 (raws loaded last iteration)
        const Hrow hC = horiz(rCp, rCt, MASK2);   // row k+1
        const Hrow hD = horiz(rDp, rDt, MASK2);   // row k+2

        poly_acc(hA, hB, hC);                     // output row k
        poly_acc(hB, hC, hD);                     // output row k+1

        hA = hC; hB = hD;
        rCp = rEp; rCt = rEt; rDp = rFp; rDt = rFt;
    }

    // ---- tail: output rows RY-2, RY-1 (raws rows RY-1 and RY already held) ----
    {
        const Hrow hC = horiz(rCp, rCt, MASK2);   // row RY-1: L1 counts
        const Hrow hD = horiz(rDp, rDt, 0ull);    // row RY: bottom halo, no L1
        poly_acc(hA, hB, hC);                     // output row RY-2
        poly_acc(hB, hC, hD);                     // output row RY-1
    }

    // fold packed pair -> scalars
    float s_lo, s_hi, l_lo, l_hi;
    unpk(ssim_acc, s_lo, s_hi);
    unpk(l1_acc,   l_lo, l_hi);
    float ssim_s = s_lo + s_hi;
    float l1_s   = l_lo + l_hi;

    // ---- warp reduce ----
    #pragma unroll
    for (int off = 16; off > 0; off >>= 1) {
        ssim_s += __shfl_down_sync(FULL_MASK, ssim_s, off);
        l1_s   += __shfl_down_sync(FULL_MASK, l1_s, off);
    }

    // ---- block reduce ----
    __shared__ float2 s_part[WPB];
    __shared__ bool   s_last;
    const int wid = threadIdx.x >> 5;
    if (lane == 0) s_part[wid] = make_float2(ssim_s, l1_s);
    __syncthreads();

    if (threadIdx.x == 0) {
        float ss = 0.0f, ll = 0.0f;
        #pragma unroll
        for (int i = 0; i < WPB; ++i) { ss += s_part[i].x; ll += s_part[i].y; }
        g_partials[blockIdx.x] = make_float2(ss, ll);
        __threadfence();
        const unsigned old = atomicAdd(&g_count, 1u);
        s_last = (old == (unsigned)(gridDim.x - 1));
    }
    __syncthreads();

    // ---- last block: deterministic final reduction ----
    if (s_last) {
        double ss = 0.0, ll = 0.0;
        for (int i = threadIdx.x; i < NBLOCKS; i += WPB * 32) {
            const float2 v = g_partials[i];
            ss += (double)v.x;
            ll += (double)v.y;
        }
        #pragma unroll
        for (int off = 16; off > 0; off >>= 1) {
            ss += __shfl_down_sync(FULL_MASK, ss, off);
            ll += __shfl_down_sync(FULL_MASK, ll, off);
        }
        __shared__ double s_ss[WPB];
        __shared__ double s_ll[WPB];
        if (lane == 0) { s_ss[wid] = ss; s_ll[wid] = ll; }
        __syncthreads();
        if (threadIdx.x == 0) {
            double tss = 0.0, tll = 0.0;
            #pragma unroll
            for (int i = 0; i < WPB; ++i) { tss += s_ss[i]; tll += s_ll[i]; }
            const double N = (double)PLANES * (double)W * (double)H;
            out[0] = (float)(0.85 * (tss / N) + 0.15 * (tll / N));
            g_count = 0;   // reset for next graph replay
        }
    }
}

extern "C" void kernel_launch(void* const* d_in, const int* in_sizes, int n_in,
                              void* d_out, int out_size)
{
    const float* pred = (const float*)d_in[0];
    const float* targ = (const float*)d_in[1];
    float* out = (float*)d_out;

    loss_main<<<NBLOCKS, WPB * 32>>>(pred, targ, out);
}

// round 16
// speedup vs baseline: 1.0737x; 1.0737x over previous
#include <cuda_runtime.h>
#include <cstdint>

#define FULL_MASK 0xffffffffu
typedef unsigned long long u64;

#define CP_COMMIT()  asm volatile("cp.async.commit_group;" ::: "memory")
#define CP_WAIT(n)   asm volatile("cp.async.wait_group " #n ";" ::: "memory")

// ---------- packed f32x2 helpers (sm_100+ SIMD fp32, PTX-only) ----------
__device__ __forceinline__ u64 pk(float lo, float hi) {
    u64 r; asm("mov.b64 %0,{%1,%2};" : "=l"(r) : "f"(lo), "f"(hi)); return r;
}
__device__ __forceinline__ void unpk(u64 v, float& lo, float& hi) {
    asm("mov.b64 {%0,%1},%2;" : "=f"(lo), "=f"(hi) : "l"(v));
}
__device__ __forceinline__ u64 add2(u64 a, u64 b) {
    u64 d; asm("add.rn.f32x2 %0,%1,%2;" : "=l"(d) : "l"(a), "l"(b)); return d;
}
__device__ __forceinline__ u64 mul2(u64 a, u64 b) {
    u64 d; asm("mul.rn.f32x2 %0,%1,%2;" : "=l"(d) : "l"(a), "l"(b)); return d;
}
__device__ __forceinline__ u64 fma2(u64 a, u64 b, u64 c) {
    u64 d; asm("fma.rn.f32x2 %0,%1,%2,%3;" : "=l"(d) : "l"(a), "l"(b), "l"(c)); return d;
}
__device__ __forceinline__ u64 abs2(u64 a) {   // clear both sign bits
    u64 d; asm("and.b64 %0,%1,0x7FFFFFFF7FFFFFFF;" : "=l"(d) : "l"(a)); return d;
}

// Problem geometry: (16, 1, 1024, 1024) fp32 pred/target, scalar fp32 out.
constexpr int W = 1024;
constexpr int H = 1024;
constexpr int PLANES = 16;

constexpr int OUTC   = 62;                 // valid outputs per 64-col warp strip
constexpr int STRIPS = 17;                 // 62*17 = 1054 >= 1024
constexpr int RY     = 32;                 // rows per warp band
constexpr int BANDS  = H / RY;             // 32
constexpr int TOTAL_WARPS = STRIPS * BANDS * PLANES;  // 8704
constexpr int WPB    = 8;                  // 256 threads per block
constexpr int NBLOCKS = TOTAL_WARPS / WPB; // 1088

// per-warp smem ring: 8 slots x (pred row 256B + targ row 256B) = 4KB/warp
constexpr int RING_BYTES_PER_WARP = 8 * 2 * 256;   // 4096

// 81-scaled SSIM constants (window SUMS instead of means; 81^2 cancels)
constexpr float C1S = 81.0f * 0.0001f;
constexpr float C2S = 81.0f * 0.0009f;

__device__ float2   g_partials[NBLOCKS];
__device__ unsigned g_count = 0;

__global__ void __launch_bounds__(WPB * 32, 4)   // <=64 regs
loss_main(const float* __restrict__ pred, const float* __restrict__ targ,
          float* __restrict__ out)
{
    __shared__ __align__(16) unsigned char ring[WPB * RING_BYTES_PER_WARP]; // 32KB

    const int warp  = blockIdx.x * WPB + (threadIdx.x >> 5);
    const int lane  = threadIdx.x & 31;
    const int wid   = threadIdx.x >> 5;
    const int strip = warp % STRIPS;
    const int band  = (warp / STRIPS) % BANDS;
    const int plane = warp / (STRIPS * BANDS);

    const int x0  = strip * OUTC + 2 * lane;       // even -> 8B aligned
    const bool xin = (x0 < W);

    const int y0 = band * RY;

    const float* __restrict__ pb0 =
        pred + (size_t)plane * (size_t)(W * H) + (size_t)y0 * W + x0;
    const float* __restrict__ tb0 =
        targ + (size_t)plane * (size_t)(W * H) + (size_t)y0 * W + x0;

    // per-warp, per-lane smem ring base (u32 shared-space address)
    const uint32_t rbase =
        (uint32_t)__cvta_generic_to_shared(ring) + wid * RING_BYTES_PER_WARP + lane * 8;

    // hoisted packed constants (warp-uniform)
    const u64 C1S2  = pk(C1S, C1S);
    const u64 C2S2  = pk(C2S, C2S);
    const u64 E182  = pk(18.0f, 18.0f);
    const u64 NINE2 = pk(9.0f, 9.0f);
    const u64 NEG12 = pk(-1.0f, -1.0f);

    const bool valid0 = ((lane > 0) || (strip == 0)) && (x0 < W);
    const bool valid1 = (lane < 31) && (x0 + 1 < W);
    const u64 MASK2 = pk(valid0 ? 1.0f : 0.0f, valid1 ? 1.0f : 0.0f);

    u64 ssim_acc = 0ull;
    u64 l1_acc   = 0ull;

    // stage row k (offset from y0, -1..RY+1) into ring slot (k+1)&7 via cp.async
    auto stage = [&](int k) {
        const uint32_t dp = rbase + (uint32_t)(((k + 1) & 7) * 512);
        const uint32_t dt = dp + 256;
        if (xin && (unsigned)(y0 + k) < (unsigned)H) {
            const float* sp = pb0 + (ptrdiff_t)k * W;
            const float* st = tb0 + (ptrdiff_t)k * W;
            asm volatile("cp.async.ca.shared.global [%0], [%1], 8;"
                         :: "r"(dp), "l"(sp) : "memory");
            asm volatile("cp.async.ca.shared.global [%0], [%1], 8;"
                         :: "r"(dt), "l"(st) : "memory");
        } else {
            asm volatile("st.shared.b64 [%0], %1;" :: "r"(dp), "l"(0ull) : "memory");
            asm volatile("st.shared.b64 [%0], %1;" :: "r"(dt), "l"(0ull) : "memory");
        }
    };

    // read row k from the ring (own lane's bytes only -> per-thread wait suffices)
    auto lds_row = [&](int k, u64& p, u64& t) {
        const uint32_t a = rbase + (uint32_t)(((k + 1) & 7) * 512);
        asm volatile("ld.shared.b64 %0, [%1];"       : "=l"(p) : "r"(a) : "memory");
        asm volatile("ld.shared.b64 %0, [%1+256];"   : "=l"(t) : "r"(a) : "memory");
    };

    // horizontal 3-sums (hp, ht, hqq = hpp+htt, hpt) + masked L1 for this row
    auto horiz = [&](u64 p64, u64 t64, u64 l1m, u64& hp, u64& ht, u64& hqq,
                     u64& hpt) {
        float px, py, tx, ty;
        unpk(p64, px, py);
        unpk(t64, tx, ty);
        float pL = __shfl_up_sync(FULL_MASK, py, 1);
        float tL = __shfl_up_sync(FULL_MASK, ty, 1);
        float pR = __shfl_down_sync(FULL_MASK, px, 1);
        float tR = __shfl_down_sync(FULL_MASK, tx, 1);
        if (lane == 0) { pL = 0.0f; tL = 0.0f; }   // image-left zero pad

        const float cp  = px + py;
        const float ct  = tx + ty;
        const float cqq = fmaf(px, px, py * py) + fmaf(tx, tx, ty * ty);
        const float cpt = fmaf(px, tx, py * ty);

        const u64 pLR = pk(pL, pR);
        const u64 tLR = pk(tL, tR);
        hp  = add2(pLR, pk(cp, cp));
        ht  = add2(tLR, pk(ct, ct));
        hqq = fma2(pLR, pLR, fma2(tLR, tLR, pk(cqq, cqq)));
        hpt = fma2(pLR, tLR, pk(cpt, cpt));

        const u64 df = abs2(fma2(t64, NEG12, p64));
        l1_acc = fma2(df, l1m, l1_acc);
    };

    // 3-row horizontal window
    u64 hp0, ht0, hqq0, hpt0;
    u64 hp1, ht1, hqq1, hpt1;
    u64 hp2, ht2, hqq2, hpt2;

    auto poly_acc = [&]() {
        const u64 SP  = add2(add2(hp0,  hp1),  hp2);
        const u64 ST  = add2(add2(ht0,  ht1),  ht2);
        const u64 Sqq = add2(add2(hqq0, hqq1), hqq2);
        const u64 SPT = add2(add2(hpt0, hpt1), hpt2);

        const u64 A   = mul2(SP, ST);
        const u64 A2  = add2(A, A);                 // 2*A
        const u64 B   = mul2(SP, SP);
        const u64 Cq  = mul2(ST, ST);
        const u64 n1  = add2(A2, C1S2);
        const u64 n2  = fma2(E182, SPT, fma2(A2, NEG12, C2S2));
        const u64 BC  = add2(B, Cq);
        const u64 d1  = add2(BC, C1S2);
        const u64 d2  = fma2(BC, NEG12, fma2(NINE2, Sqq, C2S2));
        const u64 num = mul2(n1, n2);
        const u64 den = mul2(d1, d2);    // >= C1S*C2S > 0

        float nx, ny, dx, dy;
        unpk(num, nx, ny);
        unpk(den, dx, dy);
        const float r0 = __fdividef(nx, dx);
        const float r1 = __fdividef(ny, dy);
        // ratio in [-1,1] exactly; val = 0.5 - 0.5*ratio in [0,1]; clamp no-op.
        float v0 = fmaf(r0, -0.5f, 0.5f);
        float v1 = fmaf(r1, -0.5f, 0.5f);
        ssim_acc = fma2(pk(v0, v1), MASK2, ssim_acc);
    };

    // ---- prologue: stage rows -1..3 (5 groups), build window rows -1..1 ----
    stage(-1); CP_COMMIT();
    stage(0);  CP_COMMIT();
    stage(1);  CP_COMMIT();
    stage(2);  CP_COMMIT();
    stage(3);  CP_COMMIT();
    CP_WAIT(2);                       // rows -1,0,1 complete
    {
        u64 pA, tA;
        lds_row(-1, pA, tA);
        horiz(pA, tA, 0ull,  hp0, ht0, hqq0, hpt0);   // top halo: no L1
        lds_row(0, pA, tA);
        horiz(pA, tA, MASK2, hp1, ht1, hqq1, hpt1);   // row y0
        lds_row(1, pA, tA);
        horiz(pA, tA, MASK2, hp2, ht2, hqq2, hpt2);   // row y0+1
    }

    // ---- main loop: r = 0..RY-3; stage row r+4, consume row r+2 ----
    #pragma unroll 8
    for (int r = 0; r < RY - 2; ++r) {
        stage(r + 4);
        CP_COMMIT();
        CP_WAIT(2);                   // <=2 pending (rows r+4, r+3) -> row r+2 ready

        u64 rp, rt;
        lds_row(r + 2, rp, rt);

        poly_acc();                   // output row r (window rows r-1..r+1)

        hp0 = hp1; ht0 = ht1; hqq0 = hqq1; hpt0 = hpt1;
        hp1 = hp2; ht1 = ht2; hqq1 = hqq2; hpt1 = hpt2;
        horiz(rp, rt, MASK2, hp2, ht2, hqq2, hpt2);   // rows 2..RY-1: L1 counts
    }

    // ---- tail: output rows RY-2, RY-1 ----
    poly_acc();                       // row RY-2
    CP_WAIT(0);
    {
        u64 rp, rt;
        lds_row(RY, rp, rt);          // bottom halo row
        hp0 = hp1; ht0 = ht1; hqq0 = hqq1; hpt0 = hpt1;
        hp1 = hp2; ht1 = ht2; hqq1 = hqq2; hpt1 = hpt2;
        horiz(rp, rt, 0ull, hp2, ht2, hqq2, hpt2);
    }
    poly_acc();                       // row RY-1

    // fold packed pair -> scalars
    float s_lo, s_hi, l_lo, l_hi;
    unpk(ssim_acc, s_lo, s_hi);
    unpk(l1_acc,   l_lo, l_hi);
    float ssim_s = s_lo + s_hi;
    float l1_s   = l_lo + l_hi;

    // ---- warp reduce ----
    #pragma unroll
    for (int off = 16; off > 0; off >>= 1) {
        ssim_s += __shfl_down_sync(FULL_MASK, ssim_s, off);
        l1_s   += __shfl_down_sync(FULL_MASK, l1_s, off);
    }

    // ---- block reduce ----
    __shared__ float2 s_part[WPB];
    __shared__ bool   s_last;
    if (lane == 0) s_part[wid] = make_float2(ssim_s, l1_s);
    __syncthreads();

    if (threadIdx.x == 0) {
        float ss = 0.0f, ll = 0.0f;
        #pragma unroll
        for (int i = 0; i < WPB; ++i) { ss += s_part[i].x; ll += s_part[i].y; }
        g_partials[blockIdx.x] = make_float2(ss, ll);
        __threadfence();
        const unsigned old = atomicAdd(&g_count, 1u);
        s_last = (old == (unsigned)(gridDim.x - 1));
    }
    __syncthreads();

    // ---- last block: deterministic final reduction ----
    if (s_last) {
        double ss = 0.0, ll = 0.0;
        for (int i = threadIdx.x; i < NBLOCKS; i += WPB * 32) {
            const float2 v = g_partials[i];
            ss += (double)v.x;
            ll += (double)v.y;
        }
        #pragma unroll
        for (int off = 16; off > 0; off >>= 1) {
            ss += __shfl_down_sync(FULL_MASK, ss, off);
            ll += __shfl_down_sync(FULL_MASK, ll, off);
        }
        __shared__ double s_ss[WPB];
        __shared__ double s_ll[WPB];
        if (lane == 0) { s_ss[wid] = ss; s_ll[wid] = ll; }
        __syncthreads();
        if (threadIdx.x == 0) {
            double tss = 0.0, tll = 0.0;
            #pragma unroll
            for (int i = 0; i < WPB; ++i) { tss += s_ss[i]; tll += s_ll[i]; }
            const double N = (double)PLANES * (double)W * (double)H;
            out[0] = (float)(0.85 * (tss / N) + 0.15 * (tll / N));
            g_count = 0;   // reset for next graph replay
        }
    }
}

extern "C" void kernel_launch(void* const* d_in, const int* in_sizes, int n_in,
                              void* d_out, int out_size)
{
    const float* pred = (const float*)d_in[0];
    const float* targ = (const float*)d_in[1];
    float* out = (float*)d_out;

    loss_main<<<NBLOCKS, WPB * 32>>>(pred, targ, out);
}